// round 6
// baseline (speedup 1.0000x reference)
#include <cuda_runtime.h>
#include <cuda_bf16.h>
#include <math.h>

#define N_NODES 50000
#define N_EDGES 800000
#define F_IN    128
#define HF      128     // H*F
#define NHEADS  8
#define FPH     16
#define NEG_SLOPE 0.2f

// ---------------- scratch (static device globals; no allocation) ----------------
__device__ float g_h[N_NODES * HF];        // projected features [N,128]
__device__ float g_asrc[N_NODES * NHEADS]; // per-node src logits
__device__ float g_adst[N_NODES * NHEADS]; // per-node dst logits
__device__ int   g_deg[N_NODES];           // zero-initialized; re-zeroed by scanC each run
__device__ int   g_off[N_NODES + 1];
__device__ int   g_cursor[N_NODES];
__device__ int   g_bsums[128];
__device__ int   g_csrc[N_EDGES];          // CSR: source node per slot
__device__ int   g_is64;                   // 1 if edge_index is int64, 0 if int32

__device__ __forceinline__ float lrelu(float v) { return v >= 0.f ? v : NEG_SLOPE * v; }

// ---------------- kernel: probe edge_index dtype ----------------
__global__ void detect_kernel(const void* ei_raw) {
    if (threadIdx.x != 0 || blockIdx.x != 0) return;
    const long long* e64 = (const long long*)ei_raw;
    int ok = 1;
    for (int i = 0; i < 256; i++) {
        long long v = e64[i];
        if (v < 0 || v >= N_NODES) { ok = 0; break; }
    }
    g_is64 = ok;
}

// ---------------- tensor-core gemm: h = x @ W^T (bf16x3), fused logits ----------
// block = 256 threads (8 warps as 4Mx2N), block tile 128x128, k-chunk 32.
// Each fp32 operand is split hi+lo bf16; D += Ah*Bh + Ah*Bl + Al*Bh (fp32 acc).
#define SMS 20   // smem row stride in uints (40 bf16) -> conflict-free frags

__device__ __forceinline__ void cvt_split(float a, float b, unsigned& hi, unsigned& lo) {
    __nv_bfloat16 ah = __float2bfloat16(a), bh = __float2bfloat16(b);
    float ar = a - __bfloat162float(ah);
    float br = b - __bfloat162float(bh);
    __nv_bfloat16 al = __float2bfloat16(ar), bl = __float2bfloat16(br);
    hi = ((unsigned)__bfloat16_as_ushort(bh) << 16) | (unsigned)__bfloat16_as_ushort(ah);
    lo = ((unsigned)__bfloat16_as_ushort(bl) << 16) | (unsigned)__bfloat16_as_ushort(al);
}

#define MMA_BF16(acc, a, b0, b1)                                              \
    asm volatile("mma.sync.aligned.m16n8k16.row.col.f32.bf16.bf16.f32 "       \
                 "{%0,%1,%2,%3}, {%4,%5,%6,%7}, {%8,%9}, {%0,%1,%2,%3};"      \
                 : "+f"((acc)[0]), "+f"((acc)[1]), "+f"((acc)[2]), "+f"((acc)[3]) \
                 : "r"((a)[0]), "r"((a)[1]), "r"((a)[2]), "r"((a)[3]),        \
                   "r"(b0), "r"(b1))

__global__ __launch_bounds__(256) void gemm_mma_kernel(
    const float* __restrict__ x, const float* __restrict__ W,
    const float* __restrict__ att_src, const float* __restrict__ att_dst)
{
    __shared__ unsigned Ah[128][SMS], Al[128][SMS];   // x tile   [m][k-pairs]
    __shared__ unsigned Bh[128][SMS], Bl[128][SMS];   // W tile   [n][k-pairs]

    int t    = threadIdx.x;
    int lane = t & 31;
    int wid  = t >> 5;
    int wr   = wid & 3;          // M group (32 rows)
    int wc   = wid >> 2;         // N group (64 cols)
    int q    = lane & 3;
    int gr   = lane >> 2;        // 0..7
    int m0   = blockIdx.x * 128;

    float acc[2][8][4];
    #pragma unroll
    for (int a = 0; a < 2; a++)
        #pragma unroll
        for (int b = 0; b < 8; b++)
            #pragma unroll
            for (int c = 0; c < 4; c++) acc[a][b][c] = 0.f;

    for (int ch = 0; ch < 4; ch++) {
        int k0 = ch * 32;
        __syncthreads();
        // load + convert x and W k-slices (each 128 rows x 8 float4)
        #pragma unroll
        for (int i = 0; i < 4; i++) {
            int idx = t + 256 * i;       // 0..1023
            int row = idx >> 3;
            int kq  = idx & 7;
            // x
            int gm = m0 + row;
            float4 v = make_float4(0.f, 0.f, 0.f, 0.f);
            if (gm < N_NODES) v = *(const float4*)&x[gm * F_IN + k0 + kq * 4];
            unsigned h0, l0, h1, l1;
            cvt_split(v.x, v.y, h0, l0);
            cvt_split(v.z, v.w, h1, l1);
            Ah[row][kq * 2] = h0; Ah[row][kq * 2 + 1] = h1;
            Al[row][kq * 2] = l0; Al[row][kq * 2 + 1] = l1;
            // W (row = n)
            float4 wv = *(const float4*)&W[row * F_IN + k0 + kq * 4];
            cvt_split(wv.x, wv.y, h0, l0);
            cvt_split(wv.z, wv.w, h1, l1);
            Bh[row][kq * 2] = h0; Bh[row][kq * 2 + 1] = h1;
            Bl[row][kq * 2] = l0; Bl[row][kq * 2 + 1] = l1;
        }
        __syncthreads();

        #pragma unroll
        for (int step = 0; step < 2; step++) {
            int kw = step * 8 + q;
            unsigned ah[2][4], al[2][4];
            #pragma unroll
            for (int mt = 0; mt < 2; mt++) {
                int r = wr * 32 + mt * 16 + gr;
                ah[mt][0] = Ah[r][kw];     ah[mt][1] = Ah[r + 8][kw];
                ah[mt][2] = Ah[r][kw + 4]; ah[mt][3] = Ah[r + 8][kw + 4];
                al[mt][0] = Al[r][kw];     al[mt][1] = Al[r + 8][kw];
                al[mt][2] = Al[r][kw + 4]; al[mt][3] = Al[r + 8][kw + 4];
            }
            #pragma unroll
            for (int nt = 0; nt < 8; nt++) {
                int n = wc * 64 + nt * 8 + gr;
                unsigned b0h = Bh[n][kw], b1h = Bh[n][kw + 4];
                unsigned b0l = Bl[n][kw], b1l = Bl[n][kw + 4];
                #pragma unroll
                for (int mt = 0; mt < 2; mt++) {
                    MMA_BF16(acc[mt][nt], ah[mt], b0h, b1h);
                    MMA_BF16(acc[mt][nt], ah[mt], b0l, b1l);
                    MMA_BF16(acc[mt][nt], al[mt], b0h, b1h);
                }
            }
        }
    }

    // epilogue: store h + fused per-head logit dot products
    float2 asv[8], adv[8];
    #pragma unroll
    for (int nt = 0; nt < 8; nt++) {
        int head = wc * 4 + (nt >> 1);
        int fc   = (nt & 1) * 8 + q * 2;
        asv[nt] = *(const float2*)&att_src[head * FPH + fc];
        adv[nt] = *(const float2*)&att_dst[head * FPH + fc];
    }

    #pragma unroll
    for (int mt = 0; mt < 2; mt++) {
        int m = m0 + wr * 32 + mt * 16 + gr;
        bool ok0 = (m < N_NODES), ok1 = (m + 8 < N_NODES);
        float ps0[4] = {0,0,0,0}, ps1[4] = {0,0,0,0};
        float pd0[4] = {0,0,0,0}, pd1[4] = {0,0,0,0};
        #pragma unroll
        for (int nt = 0; nt < 8; nt++) {
            float* c = acc[mt][nt];
            int n = wc * 64 + nt * 8 + q * 2;
            if (ok0) *(float2*)&g_h[m * HF + n]       = make_float2(c[0], c[1]);
            if (ok1) *(float2*)&g_h[(m + 8) * HF + n] = make_float2(c[2], c[3]);
            int hh = nt >> 1;
            ps0[hh] += c[0] * asv[nt].x + c[1] * asv[nt].y;
            pd0[hh] += c[0] * adv[nt].x + c[1] * adv[nt].y;
            ps1[hh] += c[2] * asv[nt].x + c[3] * asv[nt].y;
            pd1[hh] += c[2] * adv[nt].x + c[3] * adv[nt].y;
        }
        #pragma unroll
        for (int hh = 0; hh < 4; hh++) {
            ps0[hh] += __shfl_xor_sync(0xffffffffu, ps0[hh], 1);
            ps0[hh] += __shfl_xor_sync(0xffffffffu, ps0[hh], 2);
            pd0[hh] += __shfl_xor_sync(0xffffffffu, pd0[hh], 1);
            pd0[hh] += __shfl_xor_sync(0xffffffffu, pd0[hh], 2);
            ps1[hh] += __shfl_xor_sync(0xffffffffu, ps1[hh], 1);
            ps1[hh] += __shfl_xor_sync(0xffffffffu, ps1[hh], 2);
            pd1[hh] += __shfl_xor_sync(0xffffffffu, pd1[hh], 1);
            pd1[hh] += __shfl_xor_sync(0xffffffffu, pd1[hh], 2);
        }
        if (q == 0) {
            if (ok0) {
                *(float4*)&g_asrc[m * NHEADS + wc * 4] = make_float4(ps0[0], ps0[1], ps0[2], ps0[3]);
                *(float4*)&g_adst[m * NHEADS + wc * 4] = make_float4(pd0[0], pd0[1], pd0[2], pd0[3]);
            }
            if (ok1) {
                *(float4*)&g_asrc[(m + 8) * NHEADS + wc * 4] = make_float4(ps1[0], ps1[1], ps1[2], ps1[3]);
                *(float4*)&g_adst[(m + 8) * NHEADS + wc * 4] = make_float4(pd1[0], pd1[1], pd1[2], pd1[3]);
            }
        }
    }
}

// ---------------- deg histogram: 4 edges per thread, vector loads ----------------
__global__ void deg_kernel(const void* __restrict__ ei) {
    int i = (blockIdx.x * blockDim.x + threadIdx.x) * 4;
    if (i >= N_EDGES) return;
    int d0, d1, d2, d3;
    if (g_is64) {
        const longlong2* p = (const longlong2*)((const long long*)ei + N_EDGES + i);
        longlong2 a = p[0], b = p[1];
        d0 = (int)a.x; d1 = (int)a.y; d2 = (int)b.x; d3 = (int)b.y;
    } else {
        int4 a = *(const int4*)((const int*)ei + N_EDGES + i);
        d0 = a.x; d1 = a.y; d2 = a.z; d3 = a.w;
    }
    atomicAdd(&g_deg[d0], 1);
    atomicAdd(&g_deg[d1], 1);
    atomicAdd(&g_deg[d2], 1);
    atomicAdd(&g_deg[d3], 1);
}

// ---------------- 2-kernel coalesced scan ----------------
#define SB   512
#define NBLK 98     // 98*512 = 50176 >= 50000
__global__ __launch_bounds__(SB) void scanA_kernel() {
    __shared__ int s[SB];
    int t = threadIdx.x;
    int i = blockIdx.x * SB + t;
    int v = (i < N_NODES) ? g_deg[i] : 0;
    s[t] = v;
    __syncthreads();
    #pragma unroll
    for (int off = 1; off < SB; off <<= 1) {
        int u = (t >= off) ? s[t - off] : 0;
        __syncthreads();
        s[t] += u;
        __syncthreads();
    }
    if (i < N_NODES) g_off[i] = s[t] - v;    // exclusive, block-local
    if (t == SB - 1) g_bsums[blockIdx.x] = s[t];
}

__global__ __launch_bounds__(SB) void scanC_kernel() {
    __shared__ int s[128];
    int t = threadIdx.x;
    if (t < 128) s[t] = (t < NBLK) ? g_bsums[t] : 0;
    __syncthreads();
    #pragma unroll
    for (int off = 1; off < 128; off <<= 1) {
        int u = (t >= off && t < 128) ? s[t - off] : 0;
        __syncthreads();
        if (t < 128) s[t] += u;
        __syncthreads();
    }
    int excl = (blockIdx.x == 0) ? 0 : s[blockIdx.x - 1];
    int i = blockIdx.x * SB + t;
    if (i < N_NODES) {
        int o = g_off[i] + excl;
        g_off[i]    = o;
        g_cursor[i] = o;
        g_deg[i]    = 0;                     // reset for next graph replay
    }
    if (i == 0) g_off[N_NODES] = N_EDGES;
}

// ---------------- scatter: CSR slot assignment only ----------------
__global__ void scatter_kernel(const void* __restrict__ ei) {
    int e = blockIdx.x * blockDim.x + threadIdx.x;
    if (e >= N_EDGES) return;
    int s, d;
    if (g_is64) {
        const long long* p = (const long long*)ei;
        s = (int)p[e];
        d = (int)p[N_EDGES + e];
    } else {
        const int* p = (const int*)ei;
        s = p[e];
        d = p[N_EDGES + e];
    }
    int pos = atomicAdd(&g_cursor[d], 1);
    g_csrc[pos] = s;
}

// ---------------- agg: online softmax (1 pass) + weighted gather -----------------
__global__ __launch_bounds__(256) void agg_kernel(
    const float* __restrict__ bias, float* __restrict__ out)
{
    int warp = (blockIdx.x * blockDim.x + threadIdx.x) >> 5;
    int lane = threadIdx.x & 31;
    if (warp >= N_NODES) return;
    int n   = warp;
    int beg = g_off[n];
    int end = g_off[n + 1];

    int head = lane & 7;
    int grp  = lane >> 3;
    float ad = g_adst[n * NHEADS + head];

    // pass 1: online max+sum per (head, group), 4 edge-streams in flight
    float m = -INFINITY, ssum = 0.f;
    for (int j = beg + grp; j < end; j += 4) {
        int src = g_csrc[j];
        float ev = lrelu(g_asrc[src * NHEADS + head] + ad);
        float nm = fmaxf(m, ev);
        ssum = ssum * __expf(m - nm) + __expf(ev - nm);
        m = nm;
    }
    // merge the 4 groups (guarded against empty groups: m = -inf, ssum = 0)
    #pragma unroll
    for (int d = 8; d <= 16; d <<= 1) {
        float mo = __shfl_xor_sync(0xffffffffu, m, d);
        float so = __shfl_xor_sync(0xffffffffu, ssum, d);
        float nm = fmaxf(m, mo);
        float f1 = (ssum > 0.f) ? __expf(m - nm) : 0.f;
        float f2 = (so   > 0.f) ? __expf(mo - nm) : 0.f;
        ssum = ssum * f1 + so * f2;
        m = nm;
    }
    float inv = 1.f / (ssum + 1e-16f);

    // pass 2: alpha-weighted gather, unrolled x2 for MLP
    float4 acc = make_float4(0.f, 0.f, 0.f, 0.f);
    int hsel = lane >> 2;
    int j = beg;
    for (; j + 1 < end; j += 2) {
        int src0 = g_csrc[j];
        int src1 = g_csrc[j + 1];
        float ev0 = (lane < 8) ? lrelu(g_asrc[src0 * NHEADS + lane] + ad) : 0.f;
        float ev1 = (lane < 8) ? lrelu(g_asrc[src1 * NHEADS + lane] + ad) : 0.f;
        float4 hv0 = *(const float4*)&g_h[src0 * HF + lane * 4];
        float4 hv1 = *(const float4*)&g_h[src1 * HF + lane * 4];
        float al0 = __expf(ev0 - m) * inv;
        float al1 = __expf(ev1 - m) * inv;
        float a0 = __shfl_sync(0xffffffffu, al0, hsel);
        float a1 = __shfl_sync(0xffffffffu, al1, hsel);
        acc.x += a0 * hv0.x; acc.y += a0 * hv0.y;
        acc.z += a0 * hv0.z; acc.w += a0 * hv0.w;
        acc.x += a1 * hv1.x; acc.y += a1 * hv1.y;
        acc.z += a1 * hv1.z; acc.w += a1 * hv1.w;
    }
    if (j < end) {
        int src = g_csrc[j];
        float ev = (lane < 8) ? lrelu(g_asrc[src * NHEADS + lane] + ad) : 0.f;
        float alpha = __expf(ev - m) * inv;
        float a = __shfl_sync(0xffffffffu, alpha, hsel);
        float4 hv = *(const float4*)&g_h[src * HF + lane * 4];
        acc.x += a * hv.x; acc.y += a * hv.y;
        acc.z += a * hv.z; acc.w += a * hv.w;
    }

    float4 bv = *(const float4*)&bias[lane * 4];
    float4 o = make_float4(acc.x + bv.x, acc.y + bv.y, acc.z + bv.z, acc.w + bv.w);
    *(float4*)&out[n * HF + lane * 4] = o;
}

// ---------------- launch ----------------
extern "C" void kernel_launch(void* const* d_in, const int* in_sizes, int n_in,
                              void* d_out, int out_size)
{
    const float* x = nullptr;
    const float* W = nullptr;
    const void*  ei = nullptr;
    const float* p128[3] = {nullptr, nullptr, nullptr};
    int n128 = 0;
    for (int i = 0; i < n_in; i++) {
        long long sz = in_sizes[i];
        if (sz == (long long)N_NODES * F_IN)      x  = (const float*)d_in[i];
        else if (sz == (long long)HF * F_IN)      W  = (const float*)d_in[i];
        else if (sz == 2LL * N_EDGES)             ei = d_in[i];
        else if (sz == 128 && n128 < 3)           p128[n128++] = (const float*)d_in[i];
    }
    const float* att_src = p128[0];
    const float* att_dst = p128[1];
    const float* bias    = p128[2];
    float*       out     = (float*)d_out;

    detect_kernel<<<1, 32>>>(ei);
    gemm_mma_kernel<<<(N_NODES + 127) / 128, 256>>>(x, W, att_src, att_dst);
    deg_kernel<<<(N_EDGES / 4 + 255) / 256, 256>>>(ei);
    scanA_kernel<<<NBLK, SB>>>();
    scanC_kernel<<<NBLK, SB>>>();
    scatter_kernel<<<(N_EDGES + 511) / 512, 512>>>(ei);
    agg_kernel<<<(N_NODES * 32 + 255) / 256, 256>>>(bias, out);
}

// round 7
// speedup vs baseline: 1.0009x; 1.0009x over previous
#include <cuda_runtime.h>
#include <cuda_bf16.h>
#include <math.h>

#define N_NODES 50000
#define N_EDGES 800000
#define F_IN    128
#define HF      128     // H*F
#define NHEADS  8
#define FPH     16
#define NEG_SLOPE 0.2f

// ---------------- scratch (static device globals; no allocation) ----------------
__device__ float g_h[N_NODES * HF];        // projected features [N,128]
__device__ float g_asrc[N_NODES * NHEADS]; // per-node src logits
__device__ float g_adst[N_NODES * NHEADS]; // per-node dst logits
__device__ int   g_deg[N_NODES];           // zero-initialized; re-zeroed by scanC each run
__device__ int   g_off[N_NODES + 1];
__device__ int   g_cursor[N_NODES];
__device__ int   g_bsums[128];
__device__ int   g_csrc[N_EDGES];          // CSR: source node per slot
__device__ int   g_is64;                   // 1 if edge_index is int64, 0 if int32

__device__ __forceinline__ float lrelu(float v) { return v >= 0.f ? v : NEG_SLOPE * v; }

// ---------------- kernel: probe edge_index dtype ----------------
__global__ void detect_kernel(const void* ei_raw) {
    if (threadIdx.x != 0 || blockIdx.x != 0) return;
    const long long* e64 = (const long long*)ei_raw;
    int ok = 1;
    for (int i = 0; i < 256; i++) {
        long long v = e64[i];
        if (v < 0 || v >= N_NODES) { ok = 0; break; }
    }
    g_is64 = ok;
}

// ---------------- tensor-core gemm: h = x @ W^T (bf16x3), fused logits ----------
// block = 256 threads (8 warps as 4Mx2N), block tile 128x128, k-chunk 32.
// Each fp32 operand is split hi+lo bf16; D += Ah*Bh + Ah*Bl + Al*Bh (fp32 acc).
#define SMS 20   // smem row stride in uints (40 bf16) -> conflict-free frags

__device__ __forceinline__ void cvt_split(float a, float b, unsigned& hi, unsigned& lo) {
    __nv_bfloat16 ah = __float2bfloat16(a), bh = __float2bfloat16(b);
    float ar = a - __bfloat162float(ah);
    float br = b - __bfloat162float(bh);
    __nv_bfloat16 al = __float2bfloat16(ar), bl = __float2bfloat16(br);
    hi = ((unsigned)__bfloat16_as_ushort(bh) << 16) | (unsigned)__bfloat16_as_ushort(ah);
    lo = ((unsigned)__bfloat16_as_ushort(bl) << 16) | (unsigned)__bfloat16_as_ushort(al);
}

#define MMA_BF16(acc, a, b0, b1)                                              \
    asm volatile("mma.sync.aligned.m16n8k16.row.col.f32.bf16.bf16.f32 "       \
                 "{%0,%1,%2,%3}, {%4,%5,%6,%7}, {%8,%9}, {%0,%1,%2,%3};"      \
                 : "+f"((acc)[0]), "+f"((acc)[1]), "+f"((acc)[2]), "+f"((acc)[3]) \
                 : "r"((a)[0]), "r"((a)[1]), "r"((a)[2]), "r"((a)[3]),        \
                   "r"(b0), "r"(b1))

__global__ __launch_bounds__(256) void gemm_mma_kernel(
    const float* __restrict__ x, const float* __restrict__ W,
    const float* __restrict__ att_src, const float* __restrict__ att_dst)
{
    __shared__ unsigned Ah[128][SMS], Al[128][SMS];   // x tile   [m][k-pairs]
    __shared__ unsigned Bh[128][SMS], Bl[128][SMS];   // W tile   [n][k-pairs]

    int t    = threadIdx.x;
    int lane = t & 31;
    int wid  = t >> 5;
    int wr   = wid & 3;          // M group (32 rows)
    int wc   = wid >> 2;         // N group (64 cols)
    int q    = lane & 3;
    int gr   = lane >> 2;        // 0..7
    int m0   = blockIdx.x * 128;

    float acc[2][8][4];
    #pragma unroll
    for (int a = 0; a < 2; a++)
        #pragma unroll
        for (int b = 0; b < 8; b++)
            #pragma unroll
            for (int c = 0; c < 4; c++) acc[a][b][c] = 0.f;

    for (int ch = 0; ch < 4; ch++) {
        int k0 = ch * 32;
        __syncthreads();
        // load + convert x and W k-slices (each 128 rows x 8 float4)
        #pragma unroll
        for (int i = 0; i < 4; i++) {
            int idx = t + 256 * i;       // 0..1023
            int row = idx >> 3;
            int kq  = idx & 7;
            // x
            int gm = m0 + row;
            float4 v = make_float4(0.f, 0.f, 0.f, 0.f);
            if (gm < N_NODES) v = *(const float4*)&x[gm * F_IN + k0 + kq * 4];
            unsigned h0, l0, h1, l1;
            cvt_split(v.x, v.y, h0, l0);
            cvt_split(v.z, v.w, h1, l1);
            Ah[row][kq * 2] = h0; Ah[row][kq * 2 + 1] = h1;
            Al[row][kq * 2] = l0; Al[row][kq * 2 + 1] = l1;
            // W (row = n)
            float4 wv = *(const float4*)&W[row * F_IN + k0 + kq * 4];
            cvt_split(wv.x, wv.y, h0, l0);
            cvt_split(wv.z, wv.w, h1, l1);
            Bh[row][kq * 2] = h0; Bh[row][kq * 2 + 1] = h1;
            Bl[row][kq * 2] = l0; Bl[row][kq * 2 + 1] = l1;
        }
        __syncthreads();

        #pragma unroll
        for (int step = 0; step < 2; step++) {
            int kw = step * 8 + q;
            unsigned ah[2][4], al[2][4];
            #pragma unroll
            for (int mt = 0; mt < 2; mt++) {
                int r = wr * 32 + mt * 16 + gr;
                ah[mt][0] = Ah[r][kw];     ah[mt][1] = Ah[r + 8][kw];
                ah[mt][2] = Ah[r][kw + 4]; ah[mt][3] = Ah[r + 8][kw + 4];
                al[mt][0] = Al[r][kw];     al[mt][1] = Al[r + 8][kw];
                al[mt][2] = Al[r][kw + 4]; al[mt][3] = Al[r + 8][kw + 4];
            }
            #pragma unroll
            for (int nt = 0; nt < 8; nt++) {
                int n = wc * 64 + nt * 8 + gr;
                unsigned b0h = Bh[n][kw], b1h = Bh[n][kw + 4];
                unsigned b0l = Bl[n][kw], b1l = Bl[n][kw + 4];
                #pragma unroll
                for (int mt = 0; mt < 2; mt++) {
                    MMA_BF16(acc[mt][nt], ah[mt], b0h, b1h);
                    MMA_BF16(acc[mt][nt], ah[mt], b0l, b1l);
                    MMA_BF16(acc[mt][nt], al[mt], b0h, b1h);
                }
            }
        }
    }

    // epilogue: store h + fused per-head logit dot products
    float2 asv[8], adv[8];
    #pragma unroll
    for (int nt = 0; nt < 8; nt++) {
        int head = wc * 4 + (nt >> 1);
        int fc   = (nt & 1) * 8 + q * 2;
        asv[nt] = *(const float2*)&att_src[head * FPH + fc];
        adv[nt] = *(const float2*)&att_dst[head * FPH + fc];
    }

    #pragma unroll
    for (int mt = 0; mt < 2; mt++) {
        int m = m0 + wr * 32 + mt * 16 + gr;
        bool ok0 = (m < N_NODES), ok1 = (m + 8 < N_NODES);
        float ps0[4] = {0,0,0,0}, ps1[4] = {0,0,0,0};
        float pd0[4] = {0,0,0,0}, pd1[4] = {0,0,0,0};
        #pragma unroll
        for (int nt = 0; nt < 8; nt++) {
            float* c = acc[mt][nt];
            int n = wc * 64 + nt * 8 + q * 2;
            if (ok0) *(float2*)&g_h[m * HF + n]       = make_float2(c[0], c[1]);
            if (ok1) *(float2*)&g_h[(m + 8) * HF + n] = make_float2(c[2], c[3]);
            int hh = nt >> 1;
            ps0[hh] += c[0] * asv[nt].x + c[1] * asv[nt].y;
            pd0[hh] += c[0] * adv[nt].x + c[1] * adv[nt].y;
            ps1[hh] += c[2] * asv[nt].x + c[3] * asv[nt].y;
            pd1[hh] += c[2] * adv[nt].x + c[3] * adv[nt].y;
        }
        #pragma unroll
        for (int hh = 0; hh < 4; hh++) {
            ps0[hh] += __shfl_xor_sync(0xffffffffu, ps0[hh], 1);
            ps0[hh] += __shfl_xor_sync(0xffffffffu, ps0[hh], 2);
            pd0[hh] += __shfl_xor_sync(0xffffffffu, pd0[hh], 1);
            pd0[hh] += __shfl_xor_sync(0xffffffffu, pd0[hh], 2);
            ps1[hh] += __shfl_xor_sync(0xffffffffu, ps1[hh], 1);
            ps1[hh] += __shfl_xor_sync(0xffffffffu, ps1[hh], 2);
            pd1[hh] += __shfl_xor_sync(0xffffffffu, pd1[hh], 1);
            pd1[hh] += __shfl_xor_sync(0xffffffffu, pd1[hh], 2);
        }
        if (q == 0) {
            if (ok0) {
                *(float4*)&g_asrc[m * NHEADS + wc * 4] = make_float4(ps0[0], ps0[1], ps0[2], ps0[3]);
                *(float4*)&g_adst[m * NHEADS + wc * 4] = make_float4(pd0[0], pd0[1], pd0[2], pd0[3]);
            }
            if (ok1) {
                *(float4*)&g_asrc[(m + 8) * NHEADS + wc * 4] = make_float4(ps1[0], ps1[1], ps1[2], ps1[3]);
                *(float4*)&g_adst[(m + 8) * NHEADS + wc * 4] = make_float4(pd1[0], pd1[1], pd1[2], pd1[3]);
            }
        }
    }
}

// ---------------- deg histogram: 4 edges per thread, vector loads ----------------
__global__ void deg_kernel(const void* __restrict__ ei) {
    int i = (blockIdx.x * blockDim.x + threadIdx.x) * 4;
    if (i >= N_EDGES) return;
    int d0, d1, d2, d3;
    if (g_is64) {
        const longlong2* p = (const longlong2*)((const long long*)ei + N_EDGES + i);
        longlong2 a = p[0], b = p[1];
        d0 = (int)a.x; d1 = (int)a.y; d2 = (int)b.x; d3 = (int)b.y;
    } else {
        int4 a = *(const int4*)((const int*)ei + N_EDGES + i);
        d0 = a.x; d1 = a.y; d2 = a.z; d3 = a.w;
    }
    atomicAdd(&g_deg[d0], 1);
    atomicAdd(&g_deg[d1], 1);
    atomicAdd(&g_deg[d2], 1);
    atomicAdd(&g_deg[d3], 1);
}

// ---------------- 2-kernel coalesced scan ----------------
#define SB   512
#define NBLK 98     // 98*512 = 50176 >= 50000
__global__ __launch_bounds__(SB) void scanA_kernel() {
    __shared__ int s[SB];
    int t = threadIdx.x;
    int i = blockIdx.x * SB + t;
    int v = (i < N_NODES) ? g_deg[i] : 0;
    s[t] = v;
    __syncthreads();
    #pragma unroll
    for (int off = 1; off < SB; off <<= 1) {
        int u = (t >= off) ? s[t - off] : 0;
        __syncthreads();
        s[t] += u;
        __syncthreads();
    }
    if (i < N_NODES) g_off[i] = s[t] - v;    // exclusive, block-local
    if (t == SB - 1) g_bsums[blockIdx.x] = s[t];
}

__global__ __launch_bounds__(SB) void scanC_kernel() {
    __shared__ int s[128];
    int t = threadIdx.x;
    if (t < 128) s[t] = (t < NBLK) ? g_bsums[t] : 0;
    __syncthreads();
    #pragma unroll
    for (int off = 1; off < 128; off <<= 1) {
        int u = (t >= off && t < 128) ? s[t - off] : 0;
        __syncthreads();
        if (t < 128) s[t] += u;
        __syncthreads();
    }
    int excl = (blockIdx.x == 0) ? 0 : s[blockIdx.x - 1];
    int i = blockIdx.x * SB + t;
    if (i < N_NODES) {
        int o = g_off[i] + excl;
        g_off[i]    = o;
        g_cursor[i] = o;
        g_deg[i]    = 0;                     // reset for next graph replay
    }
    if (i == 0) g_off[N_NODES] = N_EDGES;
}

// ---------------- scatter: CSR slot assignment only ----------------
__global__ void scatter_kernel(const void* __restrict__ ei) {
    int e = blockIdx.x * blockDim.x + threadIdx.x;
    if (e >= N_EDGES) return;
    int s, d;
    if (g_is64) {
        const long long* p = (const long long*)ei;
        s = (int)p[e];
        d = (int)p[N_EDGES + e];
    } else {
        const int* p = (const int*)ei;
        s = p[e];
        d = p[N_EDGES + e];
    }
    int pos = atomicAdd(&g_cursor[d], 1);
    g_csrc[pos] = s;
}

// ---------------- agg: online softmax (1 pass) + weighted gather -----------------
__global__ __launch_bounds__(256) void agg_kernel(
    const float* __restrict__ bias, float* __restrict__ out)
{
    int warp = (blockIdx.x * blockDim.x + threadIdx.x) >> 5;
    int lane = threadIdx.x & 31;
    if (warp >= N_NODES) return;
    int n   = warp;
    int beg = g_off[n];
    int end = g_off[n + 1];

    int head = lane & 7;
    int grp  = lane >> 3;
    float ad = g_adst[n * NHEADS + head];

    // pass 1: online max+sum per (head, group), 4 edge-streams in flight
    float m = -INFINITY, ssum = 0.f;
    for (int j = beg + grp; j < end; j += 4) {
        int src = g_csrc[j];
        float ev = lrelu(g_asrc[src * NHEADS + head] + ad);
        float nm = fmaxf(m, ev);
        ssum = ssum * __expf(m - nm) + __expf(ev - nm);
        m = nm;
    }
    // merge the 4 groups (guarded against empty groups: m = -inf, ssum = 0)
    #pragma unroll
    for (int d = 8; d <= 16; d <<= 1) {
        float mo = __shfl_xor_sync(0xffffffffu, m, d);
        float so = __shfl_xor_sync(0xffffffffu, ssum, d);
        float nm = fmaxf(m, mo);
        float f1 = (ssum > 0.f) ? __expf(m - nm) : 0.f;
        float f2 = (so   > 0.f) ? __expf(mo - nm) : 0.f;
        ssum = ssum * f1 + so * f2;
        m = nm;
    }
    float inv = 1.f / (ssum + 1e-16f);

    // pass 2: alpha-weighted gather, unrolled x2 for MLP
    float4 acc = make_float4(0.f, 0.f, 0.f, 0.f);
    int hsel = lane >> 2;
    int j = beg;
    for (; j + 1 < end; j += 2) {
        int src0 = g_csrc[j];
        int src1 = g_csrc[j + 1];
        float ev0 = (lane < 8) ? lrelu(g_asrc[src0 * NHEADS + lane] + ad) : 0.f;
        float ev1 = (lane < 8) ? lrelu(g_asrc[src1 * NHEADS + lane] + ad) : 0.f;
        float4 hv0 = *(const float4*)&g_h[src0 * HF + lane * 4];
        float4 hv1 = *(const float4*)&g_h[src1 * HF + lane * 4];
        float al0 = __expf(ev0 - m) * inv;
        float al1 = __expf(ev1 - m) * inv;
        float a0 = __shfl_sync(0xffffffffu, al0, hsel);
        float a1 = __shfl_sync(0xffffffffu, al1, hsel);
        acc.x += a0 * hv0.x; acc.y += a0 * hv0.y;
        acc.z += a0 * hv0.z; acc.w += a0 * hv0.w;
        acc.x += a1 * hv1.x; acc.y += a1 * hv1.y;
        acc.z += a1 * hv1.z; acc.w += a1 * hv1.w;
    }
    if (j < end) {
        int src = g_csrc[j];
        float ev = (lane < 8) ? lrelu(g_asrc[src * NHEADS + lane] + ad) : 0.f;
        float alpha = __expf(ev - m) * inv;
        float a = __shfl_sync(0xffffffffu, alpha, hsel);
        float4 hv = *(const float4*)&g_h[src * HF + lane * 4];
        acc.x += a * hv.x; acc.y += a * hv.y;
        acc.z += a * hv.z; acc.w += a * hv.w;
    }

    float4 bv = *(const float4*)&bias[lane * 4];
    float4 o = make_float4(acc.x + bv.x, acc.y + bv.y, acc.z + bv.z, acc.w + bv.w);
    *(float4*)&out[n * HF + lane * 4] = o;
}

// ---------------- launch ----------------
extern "C" void kernel_launch(void* const* d_in, const int* in_sizes, int n_in,
                              void* d_out, int out_size)
{
    const float* x = nullptr;
    const float* W = nullptr;
    const void*  ei = nullptr;
    const float* p128[3] = {nullptr, nullptr, nullptr};
    int n128 = 0;
    for (int i = 0; i < n_in; i++) {
        long long sz = in_sizes[i];
        if (sz == (long long)N_NODES * F_IN)      x  = (const float*)d_in[i];
        else if (sz == (long long)HF * F_IN)      W  = (const float*)d_in[i];
        else if (sz == 2LL * N_EDGES)             ei = d_in[i];
        else if (sz == 128 && n128 < 3)           p128[n128++] = (const float*)d_in[i];
    }
    const float* att_src = p128[0];
    const float* att_dst = p128[1];
    const float* bias    = p128[2];
    float*       out     = (float*)d_out;

    detect_kernel<<<1, 32>>>(ei);
    gemm_mma_kernel<<<(N_NODES + 127) / 128, 256>>>(x, W, att_src, att_dst);
    deg_kernel<<<(N_EDGES / 4 + 255) / 256, 256>>>(ei);
    scanA_kernel<<<NBLK, SB>>>();
    scanC_kernel<<<NBLK, SB>>>();
    scatter_kernel<<<(N_EDGES + 511) / 512, 512>>>(ei);
    agg_kernel<<<(N_NODES * 32 + 255) / 256, 256>>>(bias, out);
}

// round 8
// speedup vs baseline: 1.1048x; 1.1038x over previous
#include <cuda_runtime.h>
#include <cuda_bf16.h>
#include <math.h>

#define N_NODES 50000
#define N_EDGES 800000
#define F_IN    128
#define HF      128     // H*F
#define NHEADS  8
#define FPH     16
#define NEG_SLOPE 0.2f

// ---------------- scratch (static device globals; no allocation) ----------------
__device__ float g_h[N_NODES * HF];        // projected features [N,128]
__device__ float g_asrc[N_NODES * NHEADS]; // per-node src logits
__device__ float g_adst[N_NODES * NHEADS]; // per-node dst logits
__device__ int   g_deg[N_NODES];           // zero-initialized; re-zeroed by scan each run
__device__ int   g_off[N_NODES + 1];
__device__ int   g_cursor[N_NODES];
__device__ int   g_bpub[128];              // published block sums (+1); re-zeroed by deg
__device__ int   g_csrc[N_EDGES];          // CSR: source node per slot
__device__ int   g_is64;                   // 1 if edge_index is int64, 0 if int32

__device__ __forceinline__ float lrelu(float v) { return v >= 0.f ? v : NEG_SLOPE * v; }

// ---------------- kernel: probe edge_index dtype (warp-parallel) ----------------
__global__ void detect_kernel(const void* ei_raw) {
    const long long* e64 = (const long long*)ei_raw;
    int lane = threadIdx.x;
    int ok = 1;
    #pragma unroll
    for (int k = 0; k < 8; k++) {
        long long v = e64[lane * 8 + k];
        if (v < 0 || v >= N_NODES) ok = 0;
    }
    unsigned b = __ballot_sync(0xffffffffu, ok);
    if (lane == 0) g_is64 = (b == 0xffffffffu) ? 1 : 0;
}

// ---------------- tensor-core gemm: h = x @ W^T (bf16x3), fused logits ----------
#define SMS 20   // smem row stride in uints (40 bf16) -> conflict-free frags

__device__ __forceinline__ void cvt_split(float a, float b, unsigned& hi, unsigned& lo) {
    __nv_bfloat16 ah = __float2bfloat16(a), bh = __float2bfloat16(b);
    float ar = a - __bfloat162float(ah);
    float br = b - __bfloat162float(bh);
    __nv_bfloat16 al = __float2bfloat16(ar), bl = __float2bfloat16(br);
    hi = ((unsigned)__bfloat16_as_ushort(bh) << 16) | (unsigned)__bfloat16_as_ushort(ah);
    lo = ((unsigned)__bfloat16_as_ushort(bl) << 16) | (unsigned)__bfloat16_as_ushort(al);
}

#define MMA_BF16(acc, a, b0, b1)                                              \
    asm volatile("mma.sync.aligned.m16n8k16.row.col.f32.bf16.bf16.f32 "       \
                 "{%0,%1,%2,%3}, {%4,%5,%6,%7}, {%8,%9}, {%0,%1,%2,%3};"      \
                 : "+f"((acc)[0]), "+f"((acc)[1]), "+f"((acc)[2]), "+f"((acc)[3]) \
                 : "r"((a)[0]), "r"((a)[1]), "r"((a)[2]), "r"((a)[3]),        \
                   "r"(b0), "r"(b1))

__global__ __launch_bounds__(256) void gemm_mma_kernel(
    const float* __restrict__ x, const float* __restrict__ W,
    const float* __restrict__ att_src, const float* __restrict__ att_dst)
{
    __shared__ unsigned Ah[128][SMS], Al[128][SMS];   // x tile   [m][k-pairs]
    __shared__ unsigned Bh[128][SMS], Bl[128][SMS];   // W tile   [n][k-pairs]

    int t    = threadIdx.x;
    int lane = t & 31;
    int wid  = t >> 5;
    int wr   = wid & 3;          // M group (32 rows)
    int wc   = wid >> 2;         // N group (64 cols)
    int q    = lane & 3;
    int gr   = lane >> 2;        // 0..7
    int m0   = blockIdx.x * 128;

    float acc[2][8][4];
    #pragma unroll
    for (int a = 0; a < 2; a++)
        #pragma unroll
        for (int b = 0; b < 8; b++)
            #pragma unroll
            for (int c = 0; c < 4; c++) acc[a][b][c] = 0.f;

    for (int ch = 0; ch < 4; ch++) {
        int k0 = ch * 32;
        __syncthreads();
        #pragma unroll
        for (int i = 0; i < 4; i++) {
            int idx = t + 256 * i;       // 0..1023
            int row = idx >> 3;
            int kq  = idx & 7;
            int gm = m0 + row;
            float4 v = make_float4(0.f, 0.f, 0.f, 0.f);
            if (gm < N_NODES) v = *(const float4*)&x[gm * F_IN + k0 + kq * 4];
            unsigned h0, l0, h1, l1;
            cvt_split(v.x, v.y, h0, l0);
            cvt_split(v.z, v.w, h1, l1);
            Ah[row][kq * 2] = h0; Ah[row][kq * 2 + 1] = h1;
            Al[row][kq * 2] = l0; Al[row][kq * 2 + 1] = l1;
            float4 wv = *(const float4*)&W[row * F_IN + k0 + kq * 4];
            cvt_split(wv.x, wv.y, h0, l0);
            cvt_split(wv.z, wv.w, h1, l1);
            Bh[row][kq * 2] = h0; Bh[row][kq * 2 + 1] = h1;
            Bl[row][kq * 2] = l0; Bl[row][kq * 2 + 1] = l1;
        }
        __syncthreads();

        #pragma unroll
        for (int step = 0; step < 2; step++) {
            int kw = step * 8 + q;
            unsigned ah[2][4], al[2][4];
            #pragma unroll
            for (int mt = 0; mt < 2; mt++) {
                int r = wr * 32 + mt * 16 + gr;
                ah[mt][0] = Ah[r][kw];     ah[mt][1] = Ah[r + 8][kw];
                ah[mt][2] = Ah[r][kw + 4]; ah[mt][3] = Ah[r + 8][kw + 4];
                al[mt][0] = Al[r][kw];     al[mt][1] = Al[r + 8][kw];
                al[mt][2] = Al[r][kw + 4]; al[mt][3] = Al[r + 8][kw + 4];
            }
            #pragma unroll
            for (int nt = 0; nt < 8; nt++) {
                int n = wc * 64 + nt * 8 + gr;
                unsigned b0h = Bh[n][kw], b1h = Bh[n][kw + 4];
                unsigned b0l = Bl[n][kw], b1l = Bl[n][kw + 4];
                #pragma unroll
                for (int mt = 0; mt < 2; mt++) {
                    MMA_BF16(acc[mt][nt], ah[mt], b0h, b1h);
                    MMA_BF16(acc[mt][nt], ah[mt], b0l, b1l);
                    MMA_BF16(acc[mt][nt], al[mt], b0h, b1h);
                }
            }
        }
    }

    // epilogue: store h + fused per-head logit dot products
    float2 asv[8], adv[8];
    #pragma unroll
    for (int nt = 0; nt < 8; nt++) {
        int head = wc * 4 + (nt >> 1);
        int fc   = (nt & 1) * 8 + q * 2;
        asv[nt] = *(const float2*)&att_src[head * FPH + fc];
        adv[nt] = *(const float2*)&att_dst[head * FPH + fc];
    }

    #pragma unroll
    for (int mt = 0; mt < 2; mt++) {
        int m = m0 + wr * 32 + mt * 16 + gr;
        bool ok0 = (m < N_NODES), ok1 = (m + 8 < N_NODES);
        float ps0[4] = {0,0,0,0}, ps1[4] = {0,0,0,0};
        float pd0[4] = {0,0,0,0}, pd1[4] = {0,0,0,0};
        #pragma unroll
        for (int nt = 0; nt < 8; nt++) {
            float* c = acc[mt][nt];
            int n = wc * 64 + nt * 8 + q * 2;
            if (ok0) *(float2*)&g_h[m * HF + n]       = make_float2(c[0], c[1]);
            if (ok1) *(float2*)&g_h[(m + 8) * HF + n] = make_float2(c[2], c[3]);
            int hh = nt >> 1;
            ps0[hh] += c[0] * asv[nt].x + c[1] * asv[nt].y;
            pd0[hh] += c[0] * adv[nt].x + c[1] * adv[nt].y;
            ps1[hh] += c[2] * asv[nt].x + c[3] * asv[nt].y;
            pd1[hh] += c[2] * adv[nt].x + c[3] * adv[nt].y;
        }
        #pragma unroll
        for (int hh = 0; hh < 4; hh++) {
            ps0[hh] += __shfl_xor_sync(0xffffffffu, ps0[hh], 1);
            ps0[hh] += __shfl_xor_sync(0xffffffffu, ps0[hh], 2);
            pd0[hh] += __shfl_xor_sync(0xffffffffu, pd0[hh], 1);
            pd0[hh] += __shfl_xor_sync(0xffffffffu, pd0[hh], 2);
            ps1[hh] += __shfl_xor_sync(0xffffffffu, ps1[hh], 1);
            ps1[hh] += __shfl_xor_sync(0xffffffffu, ps1[hh], 2);
            pd1[hh] += __shfl_xor_sync(0xffffffffu, pd1[hh], 1);
            pd1[hh] += __shfl_xor_sync(0xffffffffu, pd1[hh], 2);
        }
        if (q == 0) {
            if (ok0) {
                *(float4*)&g_asrc[m * NHEADS + wc * 4] = make_float4(ps0[0], ps0[1], ps0[2], ps0[3]);
                *(float4*)&g_adst[m * NHEADS + wc * 4] = make_float4(pd0[0], pd0[1], pd0[2], pd0[3]);
            }
            if (ok1) {
                *(float4*)&g_asrc[(m + 8) * NHEADS + wc * 4] = make_float4(ps1[0], ps1[1], ps1[2], ps1[3]);
                *(float4*)&g_adst[(m + 8) * NHEADS + wc * 4] = make_float4(pd1[0], pd1[1], pd1[2], pd1[3]);
            }
        }
    }
}

// ---------------- deg histogram: 4 edges per thread; also resets scan flags ------
__global__ void deg_kernel(const void* __restrict__ ei) {
    int gid = blockIdx.x * blockDim.x + threadIdx.x;
    if (gid < 128) g_bpub[gid] = 0;          // reset lookback slots for this run
    int i = gid * 4;
    if (i >= N_EDGES) return;
    int d0, d1, d2, d3;
    if (g_is64) {
        const longlong2* p = (const longlong2*)((const long long*)ei + N_EDGES + i);
        longlong2 a = p[0], b = p[1];
        d0 = (int)a.x; d1 = (int)a.y; d2 = (int)b.x; d3 = (int)b.y;
    } else {
        int4 a = *(const int4*)((const int*)ei + N_EDGES + i);
        d0 = a.x; d1 = a.y; d2 = a.z; d3 = a.w;
    }
    atomicAdd(&g_deg[d0], 1);
    atomicAdd(&g_deg[d1], 1);
    atomicAdd(&g_deg[d2], 1);
    atomicAdd(&g_deg[d3], 1);
}

// ---------------- single-kernel scan: warp-shuffle scan + all-resident lookback --
#define SB   512
#define NBLK 98     // 98*512 = 50176 >= 50000; 98 <= 148 SMs -> all resident
__global__ __launch_bounds__(SB) void scan_fused() {
    __shared__ int wsum[16];
    __shared__ int pre;
    int t = threadIdx.x, b = blockIdx.x;
    int lane = t & 31, w = t >> 5;
    int i = b * SB + t;
    int v = (i < N_NODES) ? g_deg[i] : 0;

    // inclusive warp scan
    int s = v;
    #pragma unroll
    for (int o = 1; o < 32; o <<= 1) {
        int u = __shfl_up_sync(0xffffffffu, s, o);
        if (lane >= o) s += u;
    }
    if (lane == 31) wsum[w] = s;
    if (t == 0) pre = 0;
    __syncthreads();
    if (w == 0) {
        int ws = (lane < 16) ? wsum[lane] : 0;
        #pragma unroll
        for (int o = 1; o < 16; o <<= 1) {
            int u = __shfl_up_sync(0xffffffffu, ws, o);
            if (lane >= o) ws += u;
        }
        if (lane < 16) wsum[lane] = ws;
    }
    __syncthreads();
    int incl  = s + (w > 0 ? wsum[w - 1] : 0);
    int total = wsum[15];

    // publish own total (+1 as ready flag) BEFORE polling -> deadlock-free
    if (t == 0) atomicExch(&g_bpub[b], total + 1);

    // lookback: threads t < b each wait for predecessor t and accumulate
    if (t < b) {
        int val;
        do { val = atomicAdd(&g_bpub[t], 0); } while (val == 0);
        atomicAdd(&pre, val - 1);
    }
    __syncthreads();

    int excl = pre + incl - v;
    if (i < N_NODES) {
        g_off[i]    = excl;
        g_cursor[i] = excl;
        g_deg[i]    = 0;                     // reset for next graph replay
    }
    if (i == 0) g_off[N_NODES] = N_EDGES;
}

// ---------------- scatter: CSR slot assignment, 2 edges/thread -------------------
__global__ void scatter_kernel(const void* __restrict__ ei) {
    int e = (blockIdx.x * blockDim.x + threadIdx.x) * 2;
    if (e >= N_EDGES) return;
    int s0, s1, d0, d1;
    if (g_is64) {
        const long long* p = (const long long*)ei;
        longlong2 sp = *(const longlong2*)&p[e];
        longlong2 dp = *(const longlong2*)&p[N_EDGES + e];
        s0 = (int)sp.x; s1 = (int)sp.y; d0 = (int)dp.x; d1 = (int)dp.y;
    } else {
        const int* p = (const int*)ei;
        int2 sp = *(const int2*)&p[e];
        int2 dp = *(const int2*)&p[N_EDGES + e];
        s0 = sp.x; s1 = sp.y; d0 = dp.x; d1 = dp.y;
    }
    int p0 = atomicAdd(&g_cursor[d0], 1);
    g_csrc[p0] = s0;
    int p1 = atomicAdd(&g_cursor[d1], 1);
    g_csrc[p1] = s1;
}

// ---------------- agg: online softmax (1 pass) + weighted gather -----------------
__global__ __launch_bounds__(256) void agg_kernel(
    const float* __restrict__ bias, float* __restrict__ out)
{
    int warp = (blockIdx.x * blockDim.x + threadIdx.x) >> 5;
    int lane = threadIdx.x & 31;
    if (warp >= N_NODES) return;
    int n   = warp;
    int beg = g_off[n];
    int end = g_off[n + 1];

    int head = lane & 7;
    int grp  = lane >> 3;
    float ad = g_adst[n * NHEADS + head];

    // pass 1: online max+sum per (head, group), 4 edge-streams in flight
    float m = -INFINITY, ssum = 0.f;
    for (int j = beg + grp; j < end; j += 4) {
        int src = g_csrc[j];
        float ev = lrelu(g_asrc[src * NHEADS + head] + ad);
        float nm = fmaxf(m, ev);
        ssum = ssum * __expf(m - nm) + __expf(ev - nm);
        m = nm;
    }
    #pragma unroll
    for (int d = 8; d <= 16; d <<= 1) {
        float mo = __shfl_xor_sync(0xffffffffu, m, d);
        float so = __shfl_xor_sync(0xffffffffu, ssum, d);
        float nm = fmaxf(m, mo);
        float f1 = (ssum > 0.f) ? __expf(m - nm) : 0.f;
        float f2 = (so   > 0.f) ? __expf(mo - nm) : 0.f;
        ssum = ssum * f1 + so * f2;
        m = nm;
    }
    float inv = 1.f / (ssum + 1e-16f);

    // pass 2: alpha-weighted gather, unrolled x2 for MLP
    float4 acc = make_float4(0.f, 0.f, 0.f, 0.f);
    int hsel = lane >> 2;
    int j = beg;
    for (; j + 1 < end; j += 2) {
        int src0 = g_csrc[j];
        int src1 = g_csrc[j + 1];
        float ev0 = (lane < 8) ? lrelu(g_asrc[src0 * NHEADS + lane] + ad) : 0.f;
        float ev1 = (lane < 8) ? lrelu(g_asrc[src1 * NHEADS + lane] + ad) : 0.f;
        float4 hv0 = *(const float4*)&g_h[src0 * HF + lane * 4];
        float4 hv1 = *(const float4*)&g_h[src1 * HF + lane * 4];
        float al0 = __expf(ev0 - m) * inv;
        float al1 = __expf(ev1 - m) * inv;
        float a0 = __shfl_sync(0xffffffffu, al0, hsel);
        float a1 = __shfl_sync(0xffffffffu, al1, hsel);
        acc.x += a0 * hv0.x; acc.y += a0 * hv0.y;
        acc.z += a0 * hv0.z; acc.w += a0 * hv0.w;
        acc.x += a1 * hv1.x; acc.y += a1 * hv1.y;
        acc.z += a1 * hv1.z; acc.w += a1 * hv1.w;
    }
    if (j < end) {
        int src = g_csrc[j];
        float ev = (lane < 8) ? lrelu(g_asrc[src * NHEADS + lane] + ad) : 0.f;
        float alpha = __expf(ev - m) * inv;
        float a = __shfl_sync(0xffffffffu, alpha, hsel);
        float4 hv = *(const float4*)&g_h[src * HF + lane * 4];
        acc.x += a * hv.x; acc.y += a * hv.y;
        acc.z += a * hv.z; acc.w += a * hv.w;
    }

    float4 bv = *(const float4*)&bias[lane * 4];
    float4 o = make_float4(acc.x + bv.x, acc.y + bv.y, acc.z + bv.z, acc.w + bv.w);
    *(float4*)&out[n * HF + lane * 4] = o;
}

// ---------------- side stream + events (created once at static init; host objects,
// identical captured work on every call) ----------------
struct GraphStreams {
    cudaStream_t side;
    cudaEvent_t ev_fork, ev_join;
    GraphStreams() {
        cudaStreamCreateWithFlags(&side, cudaStreamNonBlocking);
        cudaEventCreateWithFlags(&ev_fork, cudaEventDisableTiming);
        cudaEventCreateWithFlags(&ev_join, cudaEventDisableTiming);
    }
};
static GraphStreams g_gs;

// ---------------- launch ----------------
extern "C" void kernel_launch(void* const* d_in, const int* in_sizes, int n_in,
                              void* d_out, int out_size)
{
    const float* x = nullptr;
    const float* W = nullptr;
    const void*  ei = nullptr;
    const float* p128[3] = {nullptr, nullptr, nullptr};
    int n128 = 0;
    for (int i = 0; i < n_in; i++) {
        long long sz = in_sizes[i];
        if (sz == (long long)N_NODES * F_IN)      x  = (const float*)d_in[i];
        else if (sz == (long long)HF * F_IN)      W  = (const float*)d_in[i];
        else if (sz == 2LL * N_EDGES)             ei = d_in[i];
        else if (sz == 128 && n128 < 3)           p128[n128++] = (const float*)d_in[i];
    }
    const float* att_src = p128[0];
    const float* att_dst = p128[1];
    const float* bias    = p128[2];
    float*       out     = (float*)d_out;

    // fork: gemm on side stream, edge-prep chain on main stream
    cudaEventRecord(g_gs.ev_fork, 0);
    cudaStreamWaitEvent(g_gs.side, g_gs.ev_fork, 0);
    gemm_mma_kernel<<<(N_NODES + 127) / 128, 256, 0, g_gs.side>>>(x, W, att_src, att_dst);
    cudaEventRecord(g_gs.ev_join, g_gs.side);

    detect_kernel<<<1, 32>>>(ei);
    deg_kernel<<<(N_EDGES / 4 + 255) / 256, 256>>>(ei);
    scan_fused<<<NBLK, SB>>>();
    scatter_kernel<<<(N_EDGES / 2 + 255) / 256, 256>>>(ei);

    // join, then aggregate
    cudaStreamWaitEvent(0, g_gs.ev_join, 0);
    agg_kernel<<<(N_NODES * 32 + 255) / 256, 256>>>(bias, out);
}

// round 9
// speedup vs baseline: 1.1348x; 1.0272x over previous
#include <cuda_runtime.h>
#include <cuda_bf16.h>
#include <math.h>

#define N_NODES 50000
#define N_PAD   50176    // 392*128, covers last gemm tile
#define N_EDGES 800000
#define F_IN    128
#define HF      128     // H*F
#define NHEADS  8
#define FPH     16
#define NEG_SLOPE 0.2f

// ---------------- scratch (static device globals; no allocation) ----------------
__device__ float    g_h[N_NODES * HF];        // projected features [N,128]
__device__ float    g_asrc[N_NODES * NHEADS]; // per-node src logits
__device__ float    g_adst[N_NODES * NHEADS]; // per-node dst logits
__device__ unsigned g_xh[N_PAD * 64];         // x hi split, bf16x2 (pad rows stay 0)
__device__ unsigned g_xl[N_PAD * 64];         // x lo split
__device__ unsigned g_wh[HF * 64];            // W hi split
__device__ unsigned g_wl[HF * 64];            // W lo split
__device__ int      g_deg[N_NODES];           // zeroed by scan each run
__device__ int      g_off[N_NODES + 1];
__device__ int      g_cursor[N_NODES];
__device__ int      g_bpub[128];              // published block sums (+1); re-zeroed by deg
__device__ int      g_csrc[N_EDGES];          // CSR: source node per slot
__device__ int      g_is64;                   // 1 if edge_index is int64, 0 if int32

__device__ __forceinline__ float lrelu(float v) { return v >= 0.f ? v : NEG_SLOPE * v; }

__device__ __forceinline__ void cvt_split(float a, float b, unsigned& hi, unsigned& lo) {
    __nv_bfloat16 ah = __float2bfloat16(a), bh = __float2bfloat16(b);
    float ar = a - __bfloat162float(ah);
    float br = b - __bfloat162float(bh);
    __nv_bfloat16 al = __float2bfloat16(ar), bl = __float2bfloat16(br);
    hi = ((unsigned)__bfloat16_as_ushort(bh) << 16) | (unsigned)__bfloat16_as_ushort(ah);
    lo = ((unsigned)__bfloat16_as_ushort(bl) << 16) | (unsigned)__bfloat16_as_ushort(al);
}

// ---------------- kernel: probe edge_index dtype (warp-parallel) ----------------
__global__ void detect_kernel(const void* ei_raw) {
    const long long* e64 = (const long long*)ei_raw;
    int lane = threadIdx.x;
    int ok = 1;
    #pragma unroll
    for (int k = 0; k < 8; k++) {
        long long v = e64[lane * 8 + k];
        if (v < 0 || v >= N_NODES) ok = 0;
    }
    unsigned b = __ballot_sync(0xffffffffu, ok);
    if (lane == 0) g_is64 = (b == 0xffffffffu) ? 1 : 0;
}

// ---------------- convert: one-time bf16 hi/lo split of x and W ----------------
__global__ void convert_kernel(const float* __restrict__ x, const float* __restrict__ W) {
    int i = blockIdx.x * blockDim.x + threadIdx.x;   // float4 index
    if (i < N_NODES * F_IN / 4) {
        float4 v = *(const float4*)&x[i * 4];
        unsigned h0, l0, h1, l1;
        cvt_split(v.x, v.y, h0, l0);
        cvt_split(v.z, v.w, h1, l1);
        ((uint2*)g_xh)[i] = make_uint2(h0, h1);
        ((uint2*)g_xl)[i] = make_uint2(l0, l1);
    }
    if (i < HF * F_IN / 4) {
        float4 v = *(const float4*)&W[i * 4];
        unsigned h0, l0, h1, l1;
        cvt_split(v.x, v.y, h0, l0);
        cvt_split(v.z, v.w, h1, l1);
        ((uint2*)g_wh)[i] = make_uint2(h0, h1);
        ((uint2*)g_wl)[i] = make_uint2(l0, l1);
    }
}

// ---------------- tensor-core gemm: h = x @ W^T (bf16x3), fused logits ----------
#define SMS 20   // smem row stride in uints -> conflict-free frags

#define MMA_BF16(acc, a, b0, b1)                                              \
    asm volatile("mma.sync.aligned.m16n8k16.row.col.f32.bf16.bf16.f32 "       \
                 "{%0,%1,%2,%3}, {%4,%5,%6,%7}, {%8,%9}, {%0,%1,%2,%3};"      \
                 : "+f"((acc)[0]), "+f"((acc)[1]), "+f"((acc)[2]), "+f"((acc)[3]) \
                 : "r"((a)[0]), "r"((a)[1]), "r"((a)[2]), "r"((a)[3]),        \
                   "r"(b0), "r"(b1))

__global__ __launch_bounds__(256) void gemm_mma_kernel(
    const float* __restrict__ att_src, const float* __restrict__ att_dst)
{
    __shared__ unsigned Ah[128][SMS], Al[128][SMS];   // x tile   [m][k-pairs]
    __shared__ unsigned Bh[128][SMS], Bl[128][SMS];   // W tile   [n][k-pairs]

    int t    = threadIdx.x;
    int lane = t & 31;
    int wid  = t >> 5;
    int wr   = wid & 3;          // M group (32 rows)
    int wc   = wid >> 2;         // N group (64 cols)
    int q    = lane & 3;
    int gr   = lane >> 2;        // 0..7
    int m0   = blockIdx.x * 128;

    float acc[2][8][4];
    #pragma unroll
    for (int a = 0; a < 2; a++)
        #pragma unroll
        for (int b = 0; b < 8; b++)
            #pragma unroll
            for (int c = 0; c < 4; c++) acc[a][b][c] = 0.f;

    for (int ch = 0; ch < 4; ch++) {
        __syncthreads();
        // pure uint4 copy: 4 arrays x 128 rows x 4 uint4 = 2048 loads, 8/thread
        #pragma unroll
        for (int i = 0; i < 8; i++) {
            int idx = t + 256 * i;       // 0..2047
            int arr = idx >> 9;
            int rem = idx & 511;
            int row = rem >> 2;
            int u   = rem & 3;
            int goff = ch * 16 + u * 4;
            uint4 v;
            unsigned* dst;
            if (arr == 0)      { v = *(const uint4*)&g_xh[(m0 + row) * 64 + goff]; dst = &Ah[row][u * 4]; }
            else if (arr == 1) { v = *(const uint4*)&g_xl[(m0 + row) * 64 + goff]; dst = &Al[row][u * 4]; }
            else if (arr == 2) { v = *(const uint4*)&g_wh[row * 64 + goff];        dst = &Bh[row][u * 4]; }
            else               { v = *(const uint4*)&g_wl[row * 64 + goff];        dst = &Bl[row][u * 4]; }
            *(uint4*)dst = v;
        }
        __syncthreads();

        #pragma unroll
        for (int step = 0; step < 2; step++) {
            int kw = step * 8 + q;
            unsigned ah[2][4], al[2][4];
            #pragma unroll
            for (int mt = 0; mt < 2; mt++) {
                int r = wr * 32 + mt * 16 + gr;
                ah[mt][0] = Ah[r][kw];     ah[mt][1] = Ah[r + 8][kw];
                ah[mt][2] = Ah[r][kw + 4]; ah[mt][3] = Ah[r + 8][kw + 4];
                al[mt][0] = Al[r][kw];     al[mt][1] = Al[r + 8][kw];
                al[mt][2] = Al[r][kw + 4]; al[mt][3] = Al[r + 8][kw + 4];
            }
            #pragma unroll
            for (int nt = 0; nt < 8; nt++) {
                int n = wc * 64 + nt * 8 + gr;
                unsigned b0h = Bh[n][kw], b1h = Bh[n][kw + 4];
                unsigned b0l = Bl[n][kw], b1l = Bl[n][kw + 4];
                #pragma unroll
                for (int mt = 0; mt < 2; mt++) {
                    MMA_BF16(acc[mt][nt], ah[mt], b0h, b1h);
                    MMA_BF16(acc[mt][nt], ah[mt], b0l, b1l);
                    MMA_BF16(acc[mt][nt], al[mt], b0h, b1h);
                }
            }
        }
    }

    // epilogue: store h + fused per-head logit dot products
    float2 asv[8], adv[8];
    #pragma unroll
    for (int nt = 0; nt < 8; nt++) {
        int head = wc * 4 + (nt >> 1);
        int fc   = (nt & 1) * 8 + q * 2;
        asv[nt] = *(const float2*)&att_src[head * FPH + fc];
        adv[nt] = *(const float2*)&att_dst[head * FPH + fc];
    }

    #pragma unroll
    for (int mt = 0; mt < 2; mt++) {
        int m = m0 + wr * 32 + mt * 16 + gr;
        bool ok0 = (m < N_NODES), ok1 = (m + 8 < N_NODES);
        float ps0[4] = {0,0,0,0}, ps1[4] = {0,0,0,0};
        float pd0[4] = {0,0,0,0}, pd1[4] = {0,0,0,0};
        #pragma unroll
        for (int nt = 0; nt < 8; nt++) {
            float* c = acc[mt][nt];
            int n = wc * 64 + nt * 8 + q * 2;
            if (ok0) *(float2*)&g_h[m * HF + n]       = make_float2(c[0], c[1]);
            if (ok1) *(float2*)&g_h[(m + 8) * HF + n] = make_float2(c[2], c[3]);
            int hh = nt >> 1;
            ps0[hh] += c[0] * asv[nt].x + c[1] * asv[nt].y;
            pd0[hh] += c[0] * adv[nt].x + c[1] * adv[nt].y;
            ps1[hh] += c[2] * asv[nt].x + c[3] * asv[nt].y;
            pd1[hh] += c[2] * adv[nt].x + c[3] * adv[nt].y;
        }
        #pragma unroll
        for (int hh = 0; hh < 4; hh++) {
            ps0[hh] += __shfl_xor_sync(0xffffffffu, ps0[hh], 1);
            ps0[hh] += __shfl_xor_sync(0xffffffffu, ps0[hh], 2);
            pd0[hh] += __shfl_xor_sync(0xffffffffu, pd0[hh], 1);
            pd0[hh] += __shfl_xor_sync(0xffffffffu, pd0[hh], 2);
            ps1[hh] += __shfl_xor_sync(0xffffffffu, ps1[hh], 1);
            ps1[hh] += __shfl_xor_sync(0xffffffffu, ps1[hh], 2);
            pd1[hh] += __shfl_xor_sync(0xffffffffu, pd1[hh], 1);
            pd1[hh] += __shfl_xor_sync(0xffffffffu, pd1[hh], 2);
        }
        if (q == 0) {
            if (ok0) {
                *(float4*)&g_asrc[m * NHEADS + wc * 4] = make_float4(ps0[0], ps0[1], ps0[2], ps0[3]);
                *(float4*)&g_adst[m * NHEADS + wc * 4] = make_float4(pd0[0], pd0[1], pd0[2], pd0[3]);
            }
            if (ok1) {
                *(float4*)&g_asrc[(m + 8) * NHEADS + wc * 4] = make_float4(ps1[0], ps1[1], ps1[2], ps1[3]);
                *(float4*)&g_adst[(m + 8) * NHEADS + wc * 4] = make_float4(pd1[0], pd1[1], pd1[2], pd1[3]);
            }
        }
    }
}

// ---------------- deg histogram: 4 edges per thread; also resets scan flags ------
__global__ void deg_kernel(const void* __restrict__ ei) {
    int gid = blockIdx.x * blockDim.x + threadIdx.x;
    if (gid < 128) g_bpub[gid] = 0;          // reset lookback slots for this run
    int i = gid * 4;
    if (i >= N_EDGES) return;
    int d0, d1, d2, d3;
    if (g_is64) {
        const longlong2* p = (const longlong2*)((const long long*)ei + N_EDGES + i);
        longlong2 a = p[0], b = p[1];
        d0 = (int)a.x; d1 = (int)a.y; d2 = (int)b.x; d3 = (int)b.y;
    } else {
        int4 a = *(const int4*)((const int*)ei + N_EDGES + i);
        d0 = a.x; d1 = a.y; d2 = a.z; d3 = a.w;
    }
    atomicAdd(&g_deg[d0], 1);
    atomicAdd(&g_deg[d1], 1);
    atomicAdd(&g_deg[d2], 1);
    atomicAdd(&g_deg[d3], 1);
}

// ---------------- single-kernel scan: warp scan + warp-reduced lookback ----------
#define SB   512
#define NBLK 98     // 98*512 = 50176 >= 50000; all blocks resident, bid-ordered waits
__global__ __launch_bounds__(SB) void scan_fused() {
    __shared__ int wsum[16];
    __shared__ int pre;
    int t = threadIdx.x, b = blockIdx.x;
    int lane = t & 31, w = t >> 5;
    int i = b * SB + t;
    int v = (i < N_NODES) ? g_deg[i] : 0;

    // inclusive warp scan
    int s = v;
    #pragma unroll
    for (int o = 1; o < 32; o <<= 1) {
        int u = __shfl_up_sync(0xffffffffu, s, o);
        if (lane >= o) s += u;
    }
    if (lane == 31) wsum[w] = s;
    __syncthreads();
    if (w == 0) {
        int ws = (lane < 16) ? wsum[lane] : 0;
        #pragma unroll
        for (int o = 1; o < 16; o <<= 1) {
            int u = __shfl_up_sync(0xffffffffu, ws, o);
            if (lane >= o) ws += u;
        }
        if (lane < 16) wsum[lane] = ws;
    }
    __syncthreads();
    int incl  = s + (w > 0 ? wsum[w - 1] : 0);
    int total = wsum[15];

    // publish own total (+1 as ready flag) BEFORE polling -> deadlock-free
    if (t == 0) atomicExch(&g_bpub[b], total + 1);

    // lookback: warp 1 polls predecessors (<=4 per lane), warp-reduces
    if (w == 1) {
        int sum = 0;
        for (int p = lane; p < b; p += 32) {
            int val;
            do { val = *(volatile int*)&g_bpub[p]; } while (val == 0);
            sum += val - 1;
        }
        #pragma unroll
        for (int o = 16; o > 0; o >>= 1)
            sum += __shfl_xor_sync(0xffffffffu, sum, o);
        if (lane == 0) pre = sum;
    }
    __syncthreads();

    int excl = pre + incl - v;
    if (i < N_NODES) {
        g_off[i]    = excl;
        g_cursor[i] = excl;
        g_deg[i]    = 0;                     // reset for next graph replay
    }
    if (i == 0) g_off[N_NODES] = N_EDGES;
}

// ---------------- scatter: CSR slot assignment, 2 edges/thread -------------------
__global__ void scatter_kernel(const void* __restrict__ ei) {
    int e = (blockIdx.x * blockDim.x + threadIdx.x) * 2;
    if (e >= N_EDGES) return;
    int s0, s1, d0, d1;
    if (g_is64) {
        const long long* p = (const long long*)ei;
        longlong2 sp = *(const longlong2*)&p[e];
        longlong2 dp = *(const longlong2*)&p[N_EDGES + e];
        s0 = (int)sp.x; s1 = (int)sp.y; d0 = (int)dp.x; d1 = (int)dp.y;
    } else {
        const int* p = (const int*)ei;
        int2 sp = *(const int2*)&p[e];
        int2 dp = *(const int2*)&p[N_EDGES + e];
        s0 = sp.x; s1 = sp.y; d0 = dp.x; d1 = dp.y;
    }
    int p0 = atomicAdd(&g_cursor[d0], 1);
    g_csrc[p0] = s0;
    int p1 = atomicAdd(&g_cursor[d1], 1);
    g_csrc[p1] = s1;
}

// ---------------- agg: single-pass flash softmax + weighted gather ---------------
// one warp per destination node. Per-head online (m, ssum) lives in lanes 0..7;
// acc covers 128 features (float4/lane); rescale factor broadcast via shfl.
__global__ __launch_bounds__(256) void agg_kernel(
    const float* __restrict__ bias, float* __restrict__ out)
{
    int warp = (blockIdx.x * blockDim.x + threadIdx.x) >> 5;
    int lane = threadIdx.x & 31;
    if (warp >= N_NODES) return;
    int n   = warp;
    int beg = g_off[n];
    int end = g_off[n + 1];

    float ad = g_adst[n * NHEADS + (lane & 7)];
    int hsel = lane >> 2;

    float m = -INFINITY, ssum = 0.f;
    float4 acc = make_float4(0.f, 0.f, 0.f, 0.f);

    int j = beg;
    for (; j + 3 < end; j += 4) {
        int src0 = g_csrc[j],     src1 = g_csrc[j + 1];
        int src2 = g_csrc[j + 2], src3 = g_csrc[j + 3];
        float4 hv0 = *(const float4*)&g_h[src0 * HF + lane * 4];
        float4 hv1 = *(const float4*)&g_h[src1 * HF + lane * 4];
        float4 hv2 = *(const float4*)&g_h[src2 * HF + lane * 4];
        float4 hv3 = *(const float4*)&g_h[src3 * HF + lane * 4];
        float ev0 = (lane < 8) ? lrelu(g_asrc[src0 * NHEADS + lane] + ad) : 0.f;
        float ev1 = (lane < 8) ? lrelu(g_asrc[src1 * NHEADS + lane] + ad) : 0.f;
        float ev2 = (lane < 8) ? lrelu(g_asrc[src2 * NHEADS + lane] + ad) : 0.f;
        float ev3 = (lane < 8) ? lrelu(g_asrc[src3 * NHEADS + lane] + ad) : 0.f;
        float nm = fmaxf(fmaxf(m, fmaxf(ev0, ev1)), fmaxf(ev2, ev3));
        float f  = __expf(m - nm);
        float p0 = __expf(ev0 - nm);
        float p1 = __expf(ev1 - nm);
        float p2 = __expf(ev2 - nm);
        float p3 = __expf(ev3 - nm);
        ssum = ssum * f + (p0 + p1) + (p2 + p3);
        m = nm;
        float fb = __shfl_sync(0xffffffffu, f,  hsel);
        float a0 = __shfl_sync(0xffffffffu, p0, hsel);
        float a1 = __shfl_sync(0xffffffffu, p1, hsel);
        float a2 = __shfl_sync(0xffffffffu, p2, hsel);
        float a3 = __shfl_sync(0xffffffffu, p3, hsel);
        acc.x = acc.x * fb + a0 * hv0.x + a1 * hv1.x + a2 * hv2.x + a3 * hv3.x;
        acc.y = acc.y * fb + a0 * hv0.y + a1 * hv1.y + a2 * hv2.y + a3 * hv3.y;
        acc.z = acc.z * fb + a0 * hv0.z + a1 * hv1.z + a2 * hv2.z + a3 * hv3.z;
        acc.w = acc.w * fb + a0 * hv0.w + a1 * hv1.w + a2 * hv2.w + a3 * hv3.w;
    }
    for (; j < end; j++) {
        int src = g_csrc[j];
        float4 hv = *(const float4*)&g_h[src * HF + lane * 4];
        float ev = (lane < 8) ? lrelu(g_asrc[src * NHEADS + lane] + ad) : 0.f;
        float nm = fmaxf(m, ev);
        float f  = __expf(m - nm);
        float p  = __expf(ev - nm);
        ssum = ssum * f + p;
        m = nm;
        float fb = __shfl_sync(0xffffffffu, f, hsel);
        float a  = __shfl_sync(0xffffffffu, p, hsel);
        acc.x = acc.x * fb + a * hv.x;
        acc.y = acc.y * fb + a * hv.y;
        acc.z = acc.z * fb + a * hv.z;
        acc.w = acc.w * fb + a * hv.w;
    }

    float inv  = 1.f / (ssum + 1e-16f);
    float invb = __shfl_sync(0xffffffffu, inv, hsel);

    float4 bv = *(const float4*)&bias[lane * 4];
    float4 o = make_float4(acc.x * invb + bv.x, acc.y * invb + bv.y,
                           acc.z * invb + bv.z, acc.w * invb + bv.w);
    *(float4*)&out[n * HF + lane * 4] = o;
}

// ---------------- side stream + events (created once at static init) ------------
struct GraphStreams {
    cudaStream_t side;
    cudaEvent_t ev_fork, ev_join;
    GraphStreams() {
        cudaStreamCreateWithFlags(&side, cudaStreamNonBlocking);
        cudaEventCreateWithFlags(&ev_fork, cudaEventDisableTiming);
        cudaEventCreateWithFlags(&ev_join, cudaEventDisableTiming);
    }
};
static GraphStreams g_gs;

// ---------------- launch ----------------
extern "C" void kernel_launch(void* const* d_in, const int* in_sizes, int n_in,
                              void* d_out, int out_size)
{
    const float* x = nullptr;
    const float* W = nullptr;
    const void*  ei = nullptr;
    const float* p128[3] = {nullptr, nullptr, nullptr};
    int n128 = 0;
    for (int i = 0; i < n_in; i++) {
        long long sz = in_sizes[i];
        if (sz == (long long)N_NODES * F_IN)      x  = (const float*)d_in[i];
        else if (sz == (long long)HF * F_IN)      W  = (const float*)d_in[i];
        else if (sz == 2LL * N_EDGES)             ei = d_in[i];
        else if (sz == 128 && n128 < 3)           p128[n128++] = (const float*)d_in[i];
    }
    const float* att_src = p128[0];
    const float* att_dst = p128[1];
    const float* bias    = p128[2];
    float*       out     = (float*)d_out;

    // fork: convert + gemm on side stream, edge-prep chain on main stream
    cudaEventRecord(g_gs.ev_fork, 0);
    cudaStreamWaitEvent(g_gs.side, g_gs.ev_fork, 0);
    convert_kernel<<<(N_NODES * F_IN / 4 + 255) / 256, 256, 0, g_gs.side>>>(x, W);
    gemm_mma_kernel<<<(N_NODES + 127) / 128, 256, 0, g_gs.side>>>(att_src, att_dst);
    cudaEventRecord(g_gs.ev_join, g_gs.side);

    detect_kernel<<<1, 32>>>(ei);
    deg_kernel<<<(N_EDGES / 4 + 255) / 256, 256>>>(ei);
    scan_fused<<<NBLK, SB>>>();
    scatter_kernel<<<(N_EDGES / 2 + 255) / 256, 256>>>(ei);

    // join, then aggregate
    cudaStreamWaitEvent(0, g_gs.ev_join, 0);
    agg_kernel<<<(N_NODES * 32 + 255) / 256, 256>>>(bias, out);
}